// round 1
// baseline (speedup 1.0000x reference)
#include <cuda_runtime.h>

#define BB 8
#define TT 4096
#define DD 256
#define HH 256
#define G4 1024   // 4*H
#define GRID_RNN 128

// 128 MB scratch for x@Wi+b, [B*T, 4H]
__device__ float g_xWi[BB * TT * G4];
// double-buffered hidden state [2][B*H]
__device__ float g_h[2][BB * HH];
// grid barrier counter
__device__ unsigned int g_bar;

// ---------------------------------------------------------------------------
// init: zero h buffers + barrier counter (required every launch: replays)
// ---------------------------------------------------------------------------
__global__ void init_kernel() {
    int i = blockIdx.x * blockDim.x + threadIdx.x;
    if (i < BB * HH) {
        g_h[0][i] = 0.f;
        g_h[1][i] = 0.f;
    }
    if (i == 0) g_bar = 0u;
}

// ---------------------------------------------------------------------------
// GEMM: g_xWi = x[B*T, D] @ Wi[D, 4H] + b
// BM=128, BN=64, BK=16, 256 threads, 8x4 register tile
// ---------------------------------------------------------------------------
__global__ void __launch_bounds__(256) gemm_kernel(const float* __restrict__ x,
                                                   const float* __restrict__ Wi,
                                                   const float* __restrict__ bias) {
    __shared__ float As[16][132];   // [k][m], stride 132 floats = 528B (16B aligned)
    __shared__ float Bs[16][64];

    int tid = threadIdx.x;
    int bm = blockIdx.y, bn = blockIdx.x;
    const float* Ablk = x + (size_t)bm * 128 * DD;
    const float* Bblk = Wi + bn * 64;

    int ty = tid >> 4;         // 0..15 -> 8 rows each
    int tx = tid & 15;         // 0..15 -> 4 cols each

    float acc[8][4];
#pragma unroll
    for (int i = 0; i < 8; i++)
#pragma unroll
        for (int j = 0; j < 4; j++) acc[i][j] = 0.f;

    for (int k0 = 0; k0 < DD; k0 += 16) {
        // load A tile: 128x16 = 512 float4, 2 per thread, store transposed
#pragma unroll
        for (int i = 0; i < 2; i++) {
            int f4  = tid * 2 + i;          // 0..511
            int row = f4 >> 2;              // 0..127
            int kq  = (f4 & 3) * 4;         // 0,4,8,12
            float4 v = *(const float4*)(Ablk + (size_t)row * DD + k0 + kq);
            As[kq + 0][row] = v.x;
            As[kq + 1][row] = v.y;
            As[kq + 2][row] = v.z;
            As[kq + 3][row] = v.w;
        }
        // load B tile: 16x64 = 256 float4, 1 per thread
        {
            int kk = tid >> 4;
            int nc = (tid & 15) * 4;
            *(float4*)&Bs[kk][nc] =
                *(const float4*)(Bblk + (size_t)(k0 + kk) * G4 + nc);
        }
        __syncthreads();

#pragma unroll
        for (int kk = 0; kk < 16; kk++) {
            float a[8], bb[4];
            *(float4*)(a)     = *(float4*)&As[kk][ty * 8];
            *(float4*)(a + 4) = *(float4*)&As[kk][ty * 8 + 4];
            *(float4*)(bb)    = *(float4*)&Bs[kk][tx * 4];
#pragma unroll
            for (int i = 0; i < 8; i++)
#pragma unroll
                for (int j = 0; j < 4; j++) acc[i][j] += a[i] * bb[j];
        }
        __syncthreads();
    }

    int col = bn * 64 + tx * 4;
    float4 bv = *(const float4*)(bias + col);
#pragma unroll
    for (int i = 0; i < 8; i++) {
        int row = bm * 128 + ty * 8 + i;
        float4 o;
        o.x = acc[i][0] + bv.x;
        o.y = acc[i][1] + bv.y;
        o.z = acc[i][2] + bv.z;
        o.w = acc[i][3] + bv.w;
        *(float4*)(g_xWi + (size_t)row * G4 + col) = o;
    }
}

// ---------------------------------------------------------------------------
// Persistent recurrent kernel. 128 CTAs x 256 threads.
// CTA = (batch b, 16 h-indices). Warp w handles h-indices k0=kbase+2w, k0+1
// -> 8 gate columns {k0, k0+256, k0+512, k0+768, k0+1, ...}.
// Lane l owns d-chunk [8l, 8l+8): 64 Wh values in registers, persistent.
// ---------------------------------------------------------------------------
__global__ void __launch_bounds__(256, 1) rnn_kernel(const float* __restrict__ Wh,
                                                     const int* __restrict__ seqlen,
                                                     float* __restrict__ y) {
    const int b     = blockIdx.x >> 4;          // 0..7
    const int kbase = (blockIdx.x & 15) * 16;   // 0..240
    const int w     = threadIdx.x >> 5;         // warp 0..7
    const int l     = threadIdx.x & 31;         // lane
    const int k0    = kbase + 2 * w;

    // preload Wh slice into registers: wh[j][d]
    // j<4 -> gate j of k0 (col = k0 + 256*j); j>=4 -> gate (j-4) of k0+1
    float wh[8][8];
#pragma unroll
    for (int j = 0; j < 8; j++) {
        int col = (j < 4) ? (k0 + 256 * j) : (k0 + 1 + 256 * (j - 4));
#pragma unroll
        for (int d = 0; d < 8; d++)
            wh[j][d] = Wh[(size_t)(l * 8 + d) * G4 + col];
    }

    const int L   = seqlen[b];
    const int myk = k0 + l;          // valid for lanes 0,1 only
    float c_state = 0.f;             // per-(b,k) cell state, lives in lane 0/1

    const float* xWib   = g_xWi + (size_t)b * TT * G4;
    float*       ybatch = y + (size_t)b * TT * HH;

    for (int t = 0; t < TT; t++) {
        const int src = (TT - 1 - t + L) & (TT - 1);

        // prefetch xWi gate pre-activations for this step (lanes 0,1)
        float xw0 = 0.f, xw1 = 0.f, xw2 = 0.f, xw3 = 0.f;
        if (l < 2) {
            const float* p = xWib + (size_t)src * G4 + myk;
            xw0 = p[0];
            xw1 = p[256];
            xw2 = p[512];
            xw3 = p[768];
        }

        // load previous h (bypass L1 — written by other CTAs)
        const float4* hp = (const float4*)(&g_h[t & 1][b * HH + l * 8]);
        float4 h0 = __ldcg(hp);
        float4 h1 = __ldcg(hp + 1);
        float hv[8] = {h0.x, h0.y, h0.z, h0.w, h1.x, h1.y, h1.z, h1.w};

        float acc[8];
#pragma unroll
        for (int j = 0; j < 8; j++) acc[j] = 0.f;
#pragma unroll
        for (int d = 0; d < 8; d++)
#pragma unroll
            for (int j = 0; j < 8; j++) acc[j] += hv[d] * wh[j][d];

        // full-warp butterfly reduce (all lanes end with totals)
#pragma unroll
        for (int m = 16; m >= 1; m >>= 1)
#pragma unroll
            for (int j = 0; j < 8; j++)
                acc[j] += __shfl_xor_sync(0xffffffffu, acc[j], m);

        if (l < 2) {
            const int off = l * 4;
            float zi = acc[off + 0] + xw0;
            float zf = acc[off + 1] + xw1;
            float zg = acc[off + 2] + xw2;
            float zo = acc[off + 3] + xw3;
            float si = 1.f / (1.f + __expf(-zi));
            float sf = 1.f / (1.f + __expf(-zf));
            float so = 1.f / (1.f + __expf(-zo));
            float tg = tanhf(zg);
            c_state  = sf * c_state + si * tg;
            float nh = so * tanhf(c_state);
            __stcg(&g_h[(t + 1) & 1][b * HH + myk], nh);
            ybatch[(size_t)src * HH + myk] = nh;
            __threadfence();   // make h visible device-wide before arrival
        }

        if (t < TT - 1) {
            __syncthreads();
            if (threadIdx.x == 0) {
                atomicAdd(&g_bar, 1u);
                const unsigned int target = (unsigned int)GRID_RNN * (t + 1);
                while (*((volatile unsigned int*)&g_bar) < target) { }
            }
            __syncthreads();
        }
    }
}

// ---------------------------------------------------------------------------
extern "C" void kernel_launch(void* const* d_in, const int* in_sizes, int n_in,
                              void* d_out, int out_size) {
    const float* x    = (const float*)d_in[0];
    const float* Wi   = (const float*)d_in[1];
    const float* Wh   = (const float*)d_in[2];
    const float* bias = (const float*)d_in[3];
    const int*   seql = (const int*)d_in[4];
    float*       y    = (float*)d_out;

    init_kernel<<<8, 256>>>();
    gemm_kernel<<<dim3(G4 / 64, (BB * TT) / 128), 256>>>(x, Wi, bias);
    rnn_kernel<<<GRID_RNN, 256>>>(Wh, seql, y);
}

// round 5
// speedup vs baseline: 1.4097x; 1.4097x over previous
#include <cuda_runtime.h>

#define BB 8
#define TT 4096
#define DD 256
#define HH 256
#define G4 1024   // 4*H
#define CLUS 8
#define NTHR 512

// 128 MB scratch for x@Wi+b, [B*T, 4H]
__device__ float g_xWi[BB * TT * G4];

// ---------------------------------------------------------------------------
// GEMM: g_xWi = x[B*T, D] @ Wi[D, 4H] + b
// BM=128, BN=64, BK=16, 256 threads, 8x4 register tile
// ---------------------------------------------------------------------------
__global__ void __launch_bounds__(256) gemm_kernel(const float* __restrict__ x,
                                                   const float* __restrict__ Wi,
                                                   const float* __restrict__ bias) {
    __shared__ float As[16][132];
    __shared__ float Bs[16][64];

    int tid = threadIdx.x;
    int bm = blockIdx.y, bn = blockIdx.x;
    const float* Ablk = x + (size_t)bm * 128 * DD;
    const float* Bblk = Wi + bn * 64;

    int ty = tid >> 4;
    int tx = tid & 15;

    float acc[8][4];
#pragma unroll
    for (int i = 0; i < 8; i++)
#pragma unroll
        for (int j = 0; j < 4; j++) acc[i][j] = 0.f;

    for (int k0 = 0; k0 < DD; k0 += 16) {
#pragma unroll
        for (int i = 0; i < 2; i++) {
            int f4  = tid * 2 + i;
            int row = f4 >> 2;
            int kq  = (f4 & 3) * 4;
            float4 v = *(const float4*)(Ablk + (size_t)row * DD + k0 + kq);
            As[kq + 0][row] = v.x;
            As[kq + 1][row] = v.y;
            As[kq + 2][row] = v.z;
            As[kq + 3][row] = v.w;
        }
        {
            int kk = tid >> 4;
            int nc = (tid & 15) * 4;
            *(float4*)&Bs[kk][nc] =
                *(const float4*)(Bblk + (size_t)(k0 + kk) * G4 + nc);
        }
        __syncthreads();

#pragma unroll
        for (int kk = 0; kk < 16; kk++) {
            float a[8], bb[4];
            *(float4*)(a)     = *(float4*)&As[kk][ty * 8];
            *(float4*)(a + 4) = *(float4*)&As[kk][ty * 8 + 4];
            *(float4*)(bb)    = *(float4*)&Bs[kk][tx * 4];
#pragma unroll
            for (int i = 0; i < 8; i++)
#pragma unroll
                for (int j = 0; j < 4; j++) acc[i][j] += a[i] * bb[j];
        }
        __syncthreads();
    }

    int col = bn * 64 + tx * 4;
    float4 bv = *(const float4*)(bias + col);
#pragma unroll
    for (int i = 0; i < 8; i++) {
        int row = bm * 128 + ty * 8 + i;
        float4 o;
        o.x = acc[i][0] + bv.x;
        o.y = acc[i][1] + bv.y;
        o.z = acc[i][2] + bv.z;
        o.w = acc[i][3] + bv.w;
        *(float4*)(g_xWi + (size_t)row * G4 + col) = o;
    }
}

// ---------------------------------------------------------------------------
// Recurrent kernel: 1 cluster (8 CTAs) per batch; grid = 64 CTAs of 512 thr.
// CTA rank r owns h-indices [32r, 32r+32). Warp w (0..15) handles k0 = 32r+2w
// and k0+1 -> 8 gate columns. Lane l owns d-chunk [8l, 8l+8): 64 Wh floats
// in registers (as 32 packed f32x2). Full h vector (256 f) lives in every
// CTA's SMEM, double buffered; per-step exchange via DSMEM stores + cluster
// barrier (arrive=release / wait=acquire orders the cluster-smem stores).
// CRITICAL: no DSMEM store may be issued after the final cluster barrier
// (peer CTA may have exited) -> last step skips the broadcast entirely.
// ---------------------------------------------------------------------------
__global__ void __launch_bounds__(NTHR, 1) __cluster_dims__(CLUS, 1, 1)
rnn_kernel(const float* __restrict__ Wh,
           const int* __restrict__ seqlen,
           float* __restrict__ y) {
    __shared__ float h_s[2][HH];

    const int b = blockIdx.x / CLUS;
    const int r = blockIdx.x % CLUS;
    const int w = threadIdx.x >> 5;
    const int l = threadIdx.x & 31;
    const int k0 = r * 32 + 2 * w;
    const int myk = k0 + l;             // meaningful for lanes 0,1
    const bool gate_lane = (l < 2);

    // ---- preload Wh slice as packed f32x2 pairs over d ----
    // j<4: gate j of column k0 ; j>=4: gate j-4 of column k0+1
    unsigned long long wh2[8][4];
#pragma unroll
    for (int j = 0; j < 8; j++) {
        int col = (j < 4) ? (k0 + 256 * j) : (k0 + 1 + 256 * (j - 4));
#pragma unroll
        for (int dd = 0; dd < 4; dd++) {
            int d = l * 8 + dd * 2;
            float lo = Wh[(size_t)d * G4 + col];
            float hi = Wh[(size_t)(d + 1) * G4 + col];
            asm("mov.b64 %0, {%1, %2};" : "=l"(wh2[j][dd]) : "f"(lo), "f"(hi));
        }
    }

    // ---- zero initial hidden state (own buffer 0 only) ----
    for (int i = threadIdx.x; i < HH; i += NTHR) h_s[0][i] = 0.f;
    __syncthreads();

    const int L = seqlen[b];
    float c_state = 0.f;
    const float* xWib = g_xWi + (size_t)b * TT * G4;
    float*       yb   = y + (size_t)b * TT * HH;

    // gate-lane xWi pointer base (safe dummy for other lanes: k=0 of batch)
    const float* xbase = xWib + (gate_lane ? myk : 0);

    // ---- precompute DSMEM peer addresses for my h slot (buffer 0) ----
    unsigned int hs_addr;
    asm("{ .reg .u64 t; cvta.to.shared.u64 t, %1; cvt.u32.u64 %0, t; }"
        : "=r"(hs_addr) : "l"((void*)h_s));
    unsigned int slot0 = hs_addr + (unsigned)myk * 4u;
    unsigned int peer[CLUS];
#pragma unroll
    for (int p = 0; p < CLUS; p++)
        asm("mapa.shared::cluster.u32 %0, %1, %2;"
            : "=r"(peer[p]) : "r"(slot0), "r"(p));

    // ---- preload xWi gates for t=0 (all lanes issue; only 0,1 meaningful) --
    float xc0, xc1, xc2, xc3;
    {
        int src0 = (TT - 1 + L) & (TT - 1);
        const float* p = xbase + (size_t)src0 * G4;
        xc0 = p[0]; xc1 = p[256]; xc2 = p[512]; xc3 = p[768];
    }

    const bool odd = (l & 1);

    for (int t = 0; t < TT; t++) {
        const int src = (TT - 1 - t + L) & (TT - 1);

        // prefetch next step's xWi (consumed next iteration; branch-free)
        float xn0 = 0.f, xn1 = 0.f, xn2 = 0.f, xn3 = 0.f;
        if (t + 1 < TT) {
            int srcn = (TT - 2 - t + L) & (TT - 1);
            const float* p = xbase + (size_t)srcn * G4;
            xn0 = p[0]; xn1 = p[256]; xn2 = p[512]; xn3 = p[768];
        }

        // load previous h (own SMEM) as packed pairs
        const unsigned long long* hp =
            (const unsigned long long*)&h_s[t & 1][l * 8];
        unsigned long long h2[4];
        h2[0] = hp[0]; h2[1] = hp[1]; h2[2] = hp[2]; h2[3] = hp[3];

        // 8 packed-f32x2 accumulators (one per gate column)
        unsigned long long acc[8];
#pragma unroll
        for (int j = 0; j < 8; j++) acc[j] = 0ull;
#pragma unroll
        for (int dd = 0; dd < 4; dd++)
#pragma unroll
            for (int j = 0; j < 8; j++)
                asm("fma.rn.f32x2 %0, %1, %2, %0;"
                    : "+l"(acc[j]) : "l"(h2[dd]), "l"(wh2[j][dd]));

        // horizontal pair-sum -> ps[8]
        float ps[8];
#pragma unroll
        for (int j = 0; j < 8; j++) {
            float lo, hi;
            asm("mov.b64 {%0, %1}, %2;" : "=f"(lo), "=f"(hi) : "l"(acc[j]));
            ps[j] = lo + hi;
        }

        // split butterfly: level xor-1 routes ps[0..3] to even lanes,
        // ps[4..7] to odd lanes (8 shfls); then 4 levels on 4 values (16).
        float v[4];
#pragma unroll
        for (int j = 0; j < 4; j++) {
            float oa = __shfl_xor_sync(0xffffffffu, ps[j], 1);
            float ob = __shfl_xor_sync(0xffffffffu, ps[j + 4], 1);
            v[j] = odd ? (ps[j + 4] + ob) : (ps[j] + oa);
        }
#pragma unroll
        for (int m = 2; m <= 16; m <<= 1)
#pragma unroll
            for (int j = 0; j < 4; j++)
                v[j] += __shfl_xor_sync(0xffffffffu, v[j], m);
        // lane 0: v = sums for gate cols of k0 ; lane 1: for k0+1

        if (gate_lane) {
            float zi = v[0] + xc0;
            float zf = v[1] + xc1;
            float zg = v[2] + xc2;
            float zo = v[3] + xc3;
            float si = 1.f / (1.f + __expf(-zi));
            float sf = 1.f / (1.f + __expf(-zf));
            float so = 1.f / (1.f + __expf(-zo));
            float tg = 2.f / (1.f + __expf(-2.f * zg)) - 1.f;
            c_state  = sf * c_state + si * tg;
            float tc = 2.f / (1.f + __expf(-2.f * c_state)) - 1.f;
            float nh = so * tc;

            // broadcast new h to every CTA in the cluster — but NEVER on the
            // last step: those stores would race with peer CTA exit.
            if (t < TT - 1) {
                unsigned int bufoff = ((t + 1) & 1) ? (unsigned)HH * 4u : 0u;
#pragma unroll
                for (int p = 0; p < CLUS; p++)
                    asm volatile("st.shared::cluster.f32 [%0], %1;"
                                 :: "r"(peer[p] + bufoff), "f"(nh) : "memory");
            }

            yb[(size_t)src * HH + myk] = nh;
        }

        if (t < TT - 1) {
            asm volatile("barrier.cluster.arrive.aligned;" ::: "memory");
            asm volatile("barrier.cluster.wait.aligned;"   ::: "memory");
        }

        xc0 = xn0; xc1 = xn1; xc2 = xn2; xc3 = xn3;
    }
}

// ---------------------------------------------------------------------------
extern "C" void kernel_launch(void* const* d_in, const int* in_sizes, int n_in,
                              void* d_out, int out_size) {
    const float* x    = (const float*)d_in[0];
    const float* Wi   = (const float*)d_in[1];
    const float* Wh   = (const float*)d_in[2];
    const float* bias = (const float*)d_in[3];
    const int*   seql = (const int*)d_in[4];
    float*       y    = (float*)d_out;

    gemm_kernel<<<dim3(G4 / 64, (BB * TT) / 128), 256>>>(x, Wi, bias);
    rnn_kernel<<<BB * CLUS, NTHR>>>(Wh, seql, y);
}

// round 6
// speedup vs baseline: 1.7036x; 1.2084x over previous
#include <cuda_runtime.h>

#define BB 8
#define TT 4096
#define DD 256
#define HH 256
#define G4 1024   // 4*H
#define CLUS 8
#define NTHR 512

// 128 MB scratch for x@Wi+b, [B*T, 4H]
__device__ float g_xWi[BB * TT * G4];

// ---------------------------------------------------------------------------
// GEMM: g_xWi = x[B*T, D] @ Wi[D, 4H] + b
// ---------------------------------------------------------------------------
__global__ void __launch_bounds__(256) gemm_kernel(const float* __restrict__ x,
                                                   const float* __restrict__ Wi,
                                                   const float* __restrict__ bias) {
    __shared__ float As[16][132];
    __shared__ float Bs[16][64];

    int tid = threadIdx.x;
    int bm = blockIdx.y, bn = blockIdx.x;
    const float* Ablk = x + (size_t)bm * 128 * DD;
    const float* Bblk = Wi + bn * 64;

    int ty = tid >> 4;
    int tx = tid & 15;

    float acc[8][4];
#pragma unroll
    for (int i = 0; i < 8; i++)
#pragma unroll
        for (int j = 0; j < 4; j++) acc[i][j] = 0.f;

    for (int k0 = 0; k0 < DD; k0 += 16) {
#pragma unroll
        for (int i = 0; i < 2; i++) {
            int f4  = tid * 2 + i;
            int row = f4 >> 2;
            int kq  = (f4 & 3) * 4;
            float4 v = *(const float4*)(Ablk + (size_t)row * DD + k0 + kq);
            As[kq + 0][row] = v.x;
            As[kq + 1][row] = v.y;
            As[kq + 2][row] = v.z;
            As[kq + 3][row] = v.w;
        }
        {
            int kk = tid >> 4;
            int nc = (tid & 15) * 4;
            *(float4*)&Bs[kk][nc] =
                *(const float4*)(Bblk + (size_t)(k0 + kk) * G4 + nc);
        }
        __syncthreads();

#pragma unroll
        for (int kk = 0; kk < 16; kk++) {
            float a[8], bb[4];
            *(float4*)(a)     = *(float4*)&As[kk][ty * 8];
            *(float4*)(a + 4) = *(float4*)&As[kk][ty * 8 + 4];
            *(float4*)(bb)    = *(float4*)&Bs[kk][tx * 4];
#pragma unroll
            for (int i = 0; i < 8; i++)
#pragma unroll
                for (int j = 0; j < 4; j++) acc[i][j] += a[i] * bb[j];
        }
        __syncthreads();
    }

    int col = bn * 64 + tx * 4;
    float4 bv = *(const float4*)(bias + col);
#pragma unroll
    for (int i = 0; i < 8; i++) {
        int row = bm * 128 + ty * 8 + i;
        float4 o;
        o.x = acc[i][0] + bv.x;
        o.y = acc[i][1] + bv.y;
        o.z = acc[i][2] + bv.z;
        o.w = acc[i][3] + bv.w;
        *(float4*)(g_xWi + (size_t)row * G4 + col) = o;
    }
}

// ---------------------------------------------------------------------------
// Recurrent kernel: 1 cluster (8 CTAs) per batch; grid = 64 CTAs of 512 thr.
// Compute phase (all 16 warps): warp w reduces 8 gate columns for h-indices
// k0=r*32+2w, k0+1; lane owns d-chunk of 8 (Wh in regs, packed f32x2).
// Full-split butterfly leaves column (l>>2)&7 on lane l; 8 lanes/warp STS
// the sums to v_s. Gate phase (warp 0 only, all 32 lanes active): lane k
// owns h-index r*32+k: LDS.128 the 4 sums, gates, c-state, DSMEM broadcast
// (128B-contiguous per peer), coalesced y STG. Warps 1-15 arrive at the
// cluster barrier immediately after bar.sync, overlapping warp 0's tail.
// No DSMEM store after the final barrier (exit race).
// ---------------------------------------------------------------------------
__global__ void __launch_bounds__(NTHR, 1) __cluster_dims__(CLUS, 1, 1)
rnn_kernel(const float* __restrict__ Wh,
           const int* __restrict__ seqlen,
           float* __restrict__ y) {
    __shared__ float  h_s[2][HH];
    __shared__ float4 v_s[32];     // [h_local] -> (i,f,g,o) pre-act sums

    const int b = blockIdx.x / CLUS;
    const int r = blockIdx.x % CLUS;
    const int w = threadIdx.x >> 5;
    const int l = threadIdx.x & 31;
    const int k0 = r * 32 + 2 * w;

    // ---- preload Wh slice as packed f32x2 pairs over d ----
    // j<4: gate j of column k0 ; j>=4: gate j-4 of column k0+1
    unsigned long long wh2[8][4];
#pragma unroll
    for (int j = 0; j < 8; j++) {
        int col = (j < 4) ? (k0 + 256 * j) : (k0 + 1 + 256 * (j - 4));
#pragma unroll
        for (int dd = 0; dd < 4; dd++) {
            int d = l * 8 + dd * 2;
            float lo = Wh[(size_t)d * G4 + col];
            float hi = Wh[(size_t)(d + 1) * G4 + col];
            asm("mov.b64 %0, {%1, %2};" : "=l"(wh2[j][dd]) : "f"(lo), "f"(hi));
        }
    }

    // ---- zero initial hidden state (buffer 0) ----
    for (int i = threadIdx.x; i < HH; i += NTHR) h_s[0][i] = 0.f;
    __syncthreads();

    const int L = seqlen[b];
    const float* xWib = g_xWi + (size_t)b * TT * G4;
    float*       yb   = y + (size_t)b * TT * HH;

    // ---- warp-0 gate-lane state ----
    const int myk = r * 32 + l;         // h-index owned by warp0 lane l
    float c_state = 0.f;

    // DSMEM peer addresses for h slot myk (buffer 0)
    unsigned int hs_addr;
    asm("{ .reg .u64 t; cvta.to.shared.u64 t, %1; cvt.u32.u64 %0, t; }"
        : "=r"(hs_addr) : "l"((void*)h_s));
    unsigned int slot0 = hs_addr + (unsigned)myk * 4u;
    unsigned int peer[CLUS];
#pragma unroll
    for (int p = 0; p < CLUS; p++)
        asm("mapa.shared::cluster.u32 %0, %1, %2;"
            : "=r"(peer[p]) : "r"(slot0), "r"(p));

    // warp0: preload xWi gates for t=0 (4 coalesced 128B loads)
    float xc0 = 0.f, xc1 = 0.f, xc2 = 0.f, xc3 = 0.f;
    if (w == 0) {
        int src0 = (TT - 1 + L) & (TT - 1);
        const float* p = xWib + (size_t)src0 * G4 + myk;
        xc0 = p[0]; xc1 = p[256]; xc2 = p[512]; xc3 = p[768];
    }

    // column this lane ends up with after the full-split butterfly
    const int cidx = (l >> 2) & 7;
    const int h_local = 2 * w + (cidx >> 2);
    const int gate    = cidx & 3;
    const bool storer = ((l & 3) == 0);

    for (int t = 0; t < TT; t++) {
        // warp0: prefetch next step's xWi (consumed next iteration)
        float xn0 = 0.f, xn1 = 0.f, xn2 = 0.f, xn3 = 0.f;
        if (w == 0 && t + 1 < TT) {
            int srcn = (TT - 2 - t + L) & (TT - 1);
            const float* p = xWib + (size_t)srcn * G4 + myk;
            xn0 = p[0]; xn1 = p[256]; xn2 = p[512]; xn3 = p[768];
        }

        // load previous h (own SMEM) as packed pairs
        const unsigned long long* hp =
            (const unsigned long long*)&h_s[t & 1][l * 8];
        unsigned long long h2[4];
        h2[0] = hp[0]; h2[1] = hp[1]; h2[2] = hp[2]; h2[3] = hp[3];

        // 8 packed-f32x2 accumulators (one per gate column)
        unsigned long long acc[8];
#pragma unroll
        for (int j = 0; j < 8; j++) acc[j] = 0ull;
#pragma unroll
        for (int dd = 0; dd < 4; dd++)
#pragma unroll
            for (int j = 0; j < 8; j++)
                asm("fma.rn.f32x2 %0, %1, %2, %0;"
                    : "+l"(acc[j]) : "l"(h2[dd]), "l"(wh2[j][dd]));

        // horizontal pair-sum -> ps[8]
        float ps[8];
#pragma unroll
        for (int j = 0; j < 8; j++) {
            float lo, hi;
            asm("mov.b64 {%0, %1}, %2;" : "=f"(lo), "=f"(hi) : "l"(acc[j]));
            ps[j] = lo + hi;
        }

        // full-split butterfly: 16 SHFL, 5 levels.
        // L1 (xor16): keep 4 values; lane bit4 -> column bit2
        float u0, u1, u2, u3;
        {
            float a0 = __shfl_xor_sync(0xffffffffu, ps[0], 16);
            float a4 = __shfl_xor_sync(0xffffffffu, ps[4], 16);
            float a1 = __shfl_xor_sync(0xffffffffu, ps[1], 16);
            float a5 = __shfl_xor_sync(0xffffffffu, ps[5], 16);
            float a2 = __shfl_xor_sync(0xffffffffu, ps[2], 16);
            float a6 = __shfl_xor_sync(0xffffffffu, ps[6], 16);
            float a3 = __shfl_xor_sync(0xffffffffu, ps[3], 16);
            float a7 = __shfl_xor_sync(0xffffffffu, ps[7], 16);
            bool hi = (l & 16);
            u0 = hi ? (ps[4] + a4) : (ps[0] + a0);
            u1 = hi ? (ps[5] + a5) : (ps[1] + a1);
            u2 = hi ? (ps[6] + a6) : (ps[2] + a2);
            u3 = hi ? (ps[7] + a7) : (ps[3] + a3);
        }
        // L2 (xor8): keep 2; lane bit3 -> column bit1
        float t0, t1;
        {
            float a0 = __shfl_xor_sync(0xffffffffu, u0, 8);
            float a2 = __shfl_xor_sync(0xffffffffu, u2, 8);
            float a1 = __shfl_xor_sync(0xffffffffu, u1, 8);
            float a3 = __shfl_xor_sync(0xffffffffu, u3, 8);
            bool hi = (l & 8);
            t0 = hi ? (u2 + a2) : (u0 + a0);
            t1 = hi ? (u3 + a3) : (u1 + a1);
        }
        // L3 (xor4): keep 1; lane bit2 -> column bit0
        float s;
        {
            float a0 = __shfl_xor_sync(0xffffffffu, t0, 4);
            float a1 = __shfl_xor_sync(0xffffffffu, t1, 4);
            s = (l & 4) ? (t1 + a1) : (t0 + a0);
        }
        // L4,L5: plain reduce within quad
        s += __shfl_xor_sync(0xffffffffu, s, 2);
        s += __shfl_xor_sync(0xffffffffu, s, 1);

        if (storer) ((float*)&v_s[h_local])[gate] = s;
        __syncthreads();

        if (w == 0) {
            float4 vv = v_s[l];
            float zi = vv.x + xc0;
            float zf = vv.y + xc1;
            float zg = vv.z + xc2;
            float zo = vv.w + xc3;
            float si = 1.f / (1.f + __expf(-zi));
            float sf = 1.f / (1.f + __expf(-zf));
            float so = 1.f / (1.f + __expf(-zo));
            float tg = 2.f / (1.f + __expf(-2.f * zg)) - 1.f;
            c_state  = sf * c_state + si * tg;
            float tc = 2.f / (1.f + __expf(-2.f * c_state)) - 1.f;
            float nh = so * tc;

            // broadcast new h to every CTA in the cluster — never on the
            // last step (would race with peer CTA exit).
            if (t < TT - 1) {
                unsigned int bufoff = ((t + 1) & 1) ? (unsigned)HH * 4u : 0u;
#pragma unroll
                for (int p = 0; p < CLUS; p++)
                    asm volatile("st.shared::cluster.f32 [%0], %1;"
                                 :: "r"(peer[p] + bufoff), "f"(nh) : "memory");
            }

            const int src = (TT - 1 - t + L) & (TT - 1);
            yb[(size_t)src * HH + myk] = nh;   // coalesced 128B store

            xc0 = xn0; xc1 = xn1; xc2 = xn2; xc3 = xn3;
        }

        if (t < TT - 1) {
            asm volatile("barrier.cluster.arrive.aligned;" ::: "memory");
            asm volatile("barrier.cluster.wait.aligned;"   ::: "memory");
        }
    }
}

// ---------------------------------------------------------------------------
extern "C" void kernel_launch(void* const* d_in, const int* in_sizes, int n_in,
                              void* d_out, int out_size) {
    const float* x    = (const float*)d_in[0];
    const float* Wi   = (const float*)d_in[1];
    const float* Wh   = (const float*)d_in[2];
    const float* bias = (const float*)d_in[3];
    const int*   seql = (const int*)d_in[4];
    float*       y    = (float*)d_out;

    gemm_kernel<<<dim3(G4 / 64, (BB * TT) / 128), 256>>>(x, Wi, bias);
    rnn_kernel<<<BB * CLUS, NTHR>>>(Wh, seql, y);
}